// round 11
// baseline (speedup 1.0000x reference)
#include <cuda_runtime.h>
#include <cuda_bf16.h>
#include <cstdint>

// AdaBoost fused classifier via legacy mma.sync TF32 (base-ISA sm_103).
//   logits[N,E] = x[N,F] @ W[E,F]^T + b
//   pred = (logit > 0); acc = sum_e pred*trunc(alpha); out = sign(acc)
// |logit| < TAU rescued by warp-cooperative exact fp32 recompute.
//
// BM=128 x BN=256(=E) x BK=32, 256 thr, warp grid 2(m) x 4(n), warp tile
// 64x64 -> B smem reuse x2 vs 32x64 (smem wf/chunk ~1344 < MMA cyc ~4096:
// tensor-bound by construction). Fragment-order smem for A and B:
//   A: thread loads 4x LDG.32 forming one fragment uint4 -> STS.128
//      (conflict-free; A-write wavefronts 256 -> 32).
//   B: prep kernel emits W in fragment order; cp.async streams it.
// Single-buffered fragments (regs ~190, no spills), 2-stage B pipeline.

#define F_DIM 512
#define E_DIM 256
#define BM 128
#define BK 32
#define NCHUNK (F_DIM / BK)   // 16
#define TAU 4e-3f
#define QCAP 512

#define A_WORDS 4096                 // 32 regions x 128 words per buffer
#define B_WORDS 8192                 // per buffer (256n x 32k, fragment order)
#define DSMEM_BYTES ((2 * A_WORDS + 2 * B_WORDS) * 4)   // 98304

// W in tf32, fragment order: word = t*8192 + (wn*4+ks)*512 + nt*64 + lane*2 + w
__device__ uint32_t g_Wfrag[E_DIM * F_DIM];

static __device__ __forceinline__ uint32_t to_tf32(float x) {
    uint32_t r;
    asm("cvt.rna.tf32.f32 %0, %1;" : "=r"(r) : "f"(x));
    return r;
}
static __device__ __forceinline__ uint32_t smem_u32(const void* p) {
    uint32_t a;
    asm("{ .reg .u64 t; cvta.to.shared.u64 t, %1; cvt.u32.u64 %0, t; }"
        : "=r"(a) : "l"(p));
    return a;
}

#define CP_ASYNC16(dst, src) \
    asm volatile("cp.async.ca.shared.global [%0], [%1], 16;" \
                 :: "r"(dst), "l"(src) : "memory")
#define CP_COMMIT() asm volatile("cp.async.commit_group;" ::: "memory")
#define CP_WAIT_ALL() asm volatile("cp.async.wait_group 0;" ::: "memory")

#define MMA_TF32(c, a, b)                                                  \
    asm volatile(                                                          \
        "mma.sync.aligned.m16n8k8.row.col.f32.tf32.tf32.f32 "              \
        "{%0,%1,%2,%3}, {%4,%5,%6,%7}, {%8,%9}, {%0,%1,%2,%3};"            \
        : "+f"((c)[0]), "+f"((c)[1]), "+f"((c)[2]), "+f"((c)[3])           \
        : "r"((a)[0]), "r"((a)[1]), "r"((a)[2]), "r"((a)[3]),              \
          "r"((b)[0]), "r"((b)[1]))

// ---- prep: convert W to tf32 AND permute into fragment order ----
__global__ void prep_kernel(const float* __restrict__ Wm) {
    int idx = blockIdx.x * blockDim.x + threadIdx.x;   // (n, k4)
    int n  = idx >> 7;
    int k4 = idx & 127;
    float4 v = *reinterpret_cast<const float4*>(Wm + (size_t)n * F_DIM + k4 * 4);
    uint32_t c0 = to_tf32(v.x), c1 = to_tf32(v.y);
    uint32_t c2 = to_tf32(v.z), c3 = to_tf32(v.w);

    int k0 = k4 * 4;
    int t  = k0 >> 5;
    int ks = (k0 >> 3) & 3;
    int w  = (k0 & 7) >> 2;
    int wn = n >> 6, nt = (n >> 3) & 7, g = n & 7;
    uint32_t base = (uint32_t)t * 8192 + (wn * 4 + ks) * 512 + nt * 64 + g * 8 + w;
    g_Wfrag[base + 0] = c0;          // tg stride 2
    g_Wfrag[base + 2] = c1;
    g_Wfrag[base + 4] = c2;
    g_Wfrag[base + 6] = c3;
}

__global__ __launch_bounds__(256, 1)
void adaboost_mma_kernel(const float* __restrict__ x,
                         const float* __restrict__ Wm,
                         const float* __restrict__ bvec,
                         const float* __restrict__ alphas,
                         float* __restrict__ out) {
    extern __shared__ uint32_t sm[];
    uint32_t* As = sm;                       // [2][32 regions][128]
    uint32_t* Bs = sm + 2 * A_WORDS;         // [2][8192] fragment order

    __shared__ float s_b[E_DIM];
    __shared__ float s_ta[E_DIM];
    __shared__ float psum[BM][4];
    __shared__ float s_rsum[BM];
    __shared__ int s_nresc;
    __shared__ uint32_t s_q[QCAP];

    const int tid  = threadIdx.x;
    const int wid  = tid >> 5;
    const int lane = tid & 31;
    const int g    = lane >> 2;
    const int tg   = lane & 3;
    const int wm   = wid & 1;      // 2 warp-rows (64 rows each)
    const int wn   = wid >> 1;     // 4 warp-cols (64 cols each)
    const int m0   = blockIdx.x * BM;

    s_b[tid]  = bvec[tid];
    s_ta[tid] = truncf(alphas[tid]);
    if (tid < BM) s_rsum[tid] = 0.0f;
    if (tid == 0) s_nresc = 0;

    const uint32_t Bs_u = smem_u32(Bs);

    float acc[4][8][4];
#pragma unroll
    for (int i = 0; i < 4; i++)
#pragma unroll
        for (int j = 0; j < 8; j++)
#pragma unroll
            for (int r = 0; r < 4; r++) acc[i][j][r] = 0.0f;

    // A commit mapping: 4 slots per thread; slot -> (region, lane2).
    // region = (rt, ks): rows rt*16..+15, k ks*8..+7.
    // fragment uint4 at word region*128 + lane2*4 holds:
    //   { x[rt*16+g2][ks*8+tg2], x[rt*16+g2+8][ks*8+tg2],
    //     x[rt*16+g2][ks*8+tg2+4], x[rt*16+g2+8][ks*8+tg2+4] }
    int a_r0[4], a_r1[4], a_k0[4];
    uint32_t a_dst[4];
#pragma unroll
    for (int l = 0; l < 4; l++) {
        int slot = tid + 256 * l;
        int region = slot >> 5, lane2 = slot & 31;
        int rt = region >> 2, ks2 = region & 3;
        int g2 = lane2 >> 2, tg2 = lane2 & 3;
        a_r0[l] = rt * 16 + g2;
        a_r1[l] = a_r0[l] + 8;
        a_k0[l] = ks2 * 8 + tg2;
        a_dst[l] = (uint32_t)(region * 128 + lane2 * 4);
    }

    // ---- prologue: chunk 0 ----
#pragma unroll
    for (int l = 0; l < 8; l++) {
        int u = tid + 256 * l;
        CP_ASYNC16(Bs_u + u * 16, (const char*)(g_Wfrag + u * 4));
    }
    CP_COMMIT();
#pragma unroll
    for (int l = 0; l < 4; l++) {
        const float* r0 = x + (size_t)(m0 + a_r0[l]) * F_DIM + a_k0[l];
        const float* r1 = x + (size_t)(m0 + a_r1[l]) * F_DIM + a_k0[l];
        uint4 o;
        o.x = to_tf32(__ldg(r0));
        o.y = to_tf32(__ldg(r1));
        o.z = to_tf32(__ldg(r0 + 4));
        o.w = to_tf32(__ldg(r1 + 4));
        *reinterpret_cast<uint4*>(As + a_dst[l]) = o;
    }

    // ---- main loop ----
    for (int t = 0; t < NCHUNK; t++) {
        const int p = t & 1;
        CP_WAIT_ALL();
        __syncthreads();

        // issue B(t+1)
        if (t + 1 < NCHUNK) {
#pragma unroll
            for (int l = 0; l < 8; l++) {
                int u = tid + 256 * l;
                CP_ASYNC16(Bs_u + ((p ^ 1) * B_WORDS) * 4 + u * 16,
                           (const char*)(g_Wfrag + (t + 1) * B_WORDS + u * 4));
            }
        }
        CP_COMMIT();

        // A(t+1) -> regs (16 LDG.32, consumed after compute)
        float pav[4][4];
        if (t + 1 < NCHUNK) {
            const int kn = (t + 1) * BK;
#pragma unroll
            for (int l = 0; l < 4; l++) {
                const float* r0 = x + (size_t)(m0 + a_r0[l]) * F_DIM + kn + a_k0[l];
                const float* r1 = x + (size_t)(m0 + a_r1[l]) * F_DIM + kn + a_k0[l];
                pav[l][0] = __ldg(r0);
                pav[l][1] = __ldg(r1);
                pav[l][2] = __ldg(r0 + 4);
                pav[l][3] = __ldg(r1 + 4);
            }
        }

        // ---- compute on buffer p ----
        const uint32_t* Ap = As + p * A_WORDS;
        const uint32_t* Bp = Bs + p * B_WORDS;
#pragma unroll
        for (int ks = 0; ks < 4; ks++) {
            uint32_t afr[4][4];
#pragma unroll
            for (int mt = 0; mt < 4; mt++) {
                uint4 q = *reinterpret_cast<const uint4*>(
                    Ap + ((wm * 4 + mt) * 4 + ks) * 128 + lane * 4);
                afr[mt][0] = q.x; afr[mt][1] = q.y;
                afr[mt][2] = q.z; afr[mt][3] = q.w;
            }
            uint32_t bfr[8][2];
#pragma unroll
            for (int nt = 0; nt < 8; nt++) {
                uint2 q = *reinterpret_cast<const uint2*>(
                    Bp + (wn * 4 + ks) * 512 + nt * 64 + lane * 2);
                bfr[nt][0] = q.x; bfr[nt][1] = q.y;
            }
#pragma unroll
            for (int mt = 0; mt < 4; mt++)
#pragma unroll
                for (int nt = 0; nt < 8; nt++)
                    MMA_TF32(acc[mt][nt], afr[mt], bfr[nt]);
        }

        // ---- commit A(t+1): cvt + STS.128, conflict-free ----
        if (t + 1 < NCHUNK) {
            uint32_t* An = As + (p ^ 1) * A_WORDS;
#pragma unroll
            for (int l = 0; l < 4; l++) {
                uint4 o;
                o.x = to_tf32(pav[l][0]);
                o.y = to_tf32(pav[l][1]);
                o.z = to_tf32(pav[l][2]);
                o.w = to_tf32(pav[l][3]);
                *reinterpret_cast<uint4*>(An + a_dst[l]) = o;
            }
        }
    }

    // ---------------- epilogue ----------------
#pragma unroll
    for (int mt = 0; mt < 4; mt++) {
#pragma unroll
        for (int half = 0; half < 2; half++) {
            int rowl = wm * 64 + mt * 16 + g + half * 8;
            float s = 0.0f;
#pragma unroll
            for (int nt = 0; nt < 8; nt++) {
#pragma unroll
                for (int j = 0; j < 2; j++) {
                    int col = wn * 64 + nt * 8 + 2 * tg + j;
                    float logit = acc[mt][nt][half * 2 + j] + s_b[col];
                    if (fabsf(logit) < TAU) {
                        int qi = atomicAdd(&s_nresc, 1);
                        if (qi < QCAP) {
                            s_q[qi] = ((uint32_t)rowl << 8) | (uint32_t)col;
                        } else {
                            const float* xr = x + (size_t)(m0 + rowl) * F_DIM;
                            const float* wr = Wm + (size_t)col * F_DIM;
                            float a = 0.0f;
                            for (int f = 0; f < F_DIM; f++)
                                a = fmaf(__ldg(xr + f), __ldg(wr + f), a);
                            if (a + s_b[col] > 0.0f) s += s_ta[col];
                        }
                    } else if (logit > 0.0f) {
                        s += s_ta[col];
                    }
                }
            }
            s += __shfl_xor_sync(0xffffffffu, s, 1);
            s += __shfl_xor_sync(0xffffffffu, s, 2);
            if (tg == 0) psum[rowl][wn] = s;
        }
    }
    __syncthreads();

    // ---- warp-cooperative rescue ----
    {
        const int nresc = min(s_nresc, QCAP);
        for (int i = wid; i < nresc; i += 8) {
            uint32_t ent = s_q[i];
            int rowl = (int)(ent >> 8);
            int col  = (int)(ent & 0xFF);
            const float* xr = x + (size_t)(m0 + rowl) * F_DIM;
            const float* wr = Wm + (size_t)col * F_DIM;
            float a0 = 0.0f, a1 = 0.0f;
#pragma unroll
            for (int j = 0; j < 16; j += 2) {
                a0 = fmaf(__ldg(xr + j * 32 + lane), __ldg(wr + j * 32 + lane), a0);
                a1 = fmaf(__ldg(xr + (j + 1) * 32 + lane), __ldg(wr + (j + 1) * 32 + lane), a1);
            }
            float a = a0 + a1;
#pragma unroll
            for (int o = 16; o > 0; o >>= 1)
                a += __shfl_xor_sync(0xffffffffu, a, o);
            if (lane == 0 && a + s_b[col] > 0.0f)
                atomicAdd(&s_rsum[rowl], s_ta[col]);
        }
    }
    __syncthreads();

    if (tid < BM) {
        float s = psum[tid][0] + psum[tid][1] + psum[tid][2] + psum[tid][3]
                + s_rsum[tid];
        out[m0 + tid] = (s > 0.0f) ? 1.0f : ((s < 0.0f) ? -1.0f : 0.0f);
    }
}

extern "C" void kernel_launch(void* const* d_in, const int* in_sizes, int n_in,
                              void* d_out, int out_size) {
    const float* x      = (const float*)d_in[0];   // [N, F]
    const float* Wm     = (const float*)d_in[1];   // [E, F]
    const float* bvec   = (const float*)d_in[2];   // [E]
    const float* alphas = (const float*)d_in[3];   // [E]
    float* out = (float*)d_out;                    // [N]

    const int E = in_sizes[2];         // 256
    const int F = in_sizes[1] / E;     // 512
    const int N = in_sizes[0] / F;     // 131072

    (void)E; (void)F;
    prep_kernel<<<(E_DIM * (F_DIM / 4)) / 256, 256>>>(Wm);

    cudaFuncSetAttribute(adaboost_mma_kernel,
                         cudaFuncAttributeMaxDynamicSharedMemorySize, DSMEM_BYTES);
    adaboost_mma_kernel<<<N / BM, 256, DSMEM_BYTES>>>(x, Wm, bvec, alphas, out);
}

// round 12
// speedup vs baseline: 1.4036x; 1.4036x over previous
#include <cuda_runtime.h>
#include <cuda_bf16.h>
#include <cstdint>

// AdaBoost fused classifier via legacy mma.sync TF32 (base-ISA sm_103).
//   logits[N,E] = x[N,F] @ W[E,F]^T + b
//   pred = (logit > 0); acc = sum_e pred*trunc(alpha); out = sign(acc)
// |logit| < TAU rescued by warp-cooperative exact fp32 recompute.
//
// R9 envelope (BM=64, 256 thr, 2 CTAs/SM, warp tile 32x64, <=128 regs) with:
//  - B fragments read DIRECTLY from fragment-ordered g_Wfrag via __ldg
//    (LDG.64 coalesced, L1-resident: W=512KB, 32KB/chunk shared by all CTAs).
//    No B smem, no cp.async, no wait -> crossbar write traffic gone.
//  - A committed as full fragments: 4x LDG.32 -> uint4 -> STS.128
//    conflict-free (A-write wavefronts 256 -> 64). One sync per chunk.

#define F_DIM 512
#define E_DIM 256
#define BM 64
#define BK 32
#define NCHUNK (F_DIM / BK)   // 16
#define TAU 4e-3f
#define QCAP 512

#define A_WORDS 2048          // 16 regions x 128 words per buffer
#define DSMEM_BYTES (2 * A_WORDS * 4)   // 16KB

// W in tf32, fragment order: word = t*8192 + (wn*4+ks)*512 + nt*64 + lane*2 + w
__device__ uint32_t g_Wfrag[E_DIM * F_DIM];

static __device__ __forceinline__ uint32_t to_tf32(float x) {
    uint32_t r;
    asm("cvt.rna.tf32.f32 %0, %1;" : "=r"(r) : "f"(x));
    return r;
}

#define MMA_TF32(c, a, b)                                                  \
    asm volatile(                                                          \
        "mma.sync.aligned.m16n8k8.row.col.f32.tf32.tf32.f32 "              \
        "{%0,%1,%2,%3}, {%4,%5,%6,%7}, {%8,%9}, {%0,%1,%2,%3};"            \
        : "+f"((c)[0]), "+f"((c)[1]), "+f"((c)[2]), "+f"((c)[3])           \
        : "r"((a)[0]), "r"((a)[1]), "r"((a)[2]), "r"((a)[3]),              \
          "r"((b)[0]), "r"((b)[1]))

// ---- prep: convert W to tf32 AND permute into fragment order ----
__global__ void prep_kernel(const float* __restrict__ Wm) {
    int idx = blockIdx.x * blockDim.x + threadIdx.x;   // (n, k4)
    int n  = idx >> 7;
    int k4 = idx & 127;
    float4 v = *reinterpret_cast<const float4*>(Wm + (size_t)n * F_DIM + k4 * 4);
    uint32_t c0 = to_tf32(v.x), c1 = to_tf32(v.y);
    uint32_t c2 = to_tf32(v.z), c3 = to_tf32(v.w);

    int k0 = k4 * 4;
    int t  = k0 >> 5;
    int ks = (k0 >> 3) & 3;
    int w  = (k0 & 7) >> 2;
    int wn = n >> 6, nt = (n >> 3) & 7, g = n & 7;
    uint32_t base = (uint32_t)t * 8192 + (wn * 4 + ks) * 512 + nt * 64 + g * 8 + w;
    g_Wfrag[base + 0] = c0;          // tg stride 2
    g_Wfrag[base + 2] = c1;
    g_Wfrag[base + 4] = c2;
    g_Wfrag[base + 6] = c3;
}

__global__ __launch_bounds__(256, 2)
void adaboost_mma_kernel(const float* __restrict__ x,
                         const float* __restrict__ Wm,
                         const float* __restrict__ bvec,
                         const float* __restrict__ alphas,
                         float* __restrict__ out) {
    extern __shared__ uint32_t As[];        // [2][16 regions][128 words]

    __shared__ float s_b[E_DIM];
    __shared__ float s_ta[E_DIM];
    __shared__ float psum[BM][4];
    __shared__ float s_rsum[BM];
    __shared__ int s_nresc;
    __shared__ uint32_t s_q[QCAP];

    const int tid  = threadIdx.x;
    const int wid  = tid >> 5;
    const int lane = tid & 31;
    const int g    = lane >> 2;
    const int tg   = lane & 3;
    const int wm   = wid & 1;      // 2 warp-rows (32 rows each)
    const int wn   = wid >> 1;     // 4 warp-cols (64 cols each)
    const int m0   = blockIdx.x * BM;

    s_b[tid]  = bvec[tid];
    s_ta[tid] = truncf(alphas[tid]);
    if (tid < BM) s_rsum[tid] = 0.0f;
    if (tid == 0) s_nresc = 0;

    float acc[2][8][4];
#pragma unroll
    for (int i = 0; i < 2; i++)
#pragma unroll
        for (int j = 0; j < 8; j++)
#pragma unroll
            for (int r = 0; r < 4; r++) acc[i][j][r] = 0.0f;

    // A commit mapping: 2 slots/thread; slot -> (region = rt*4+ks, lane2).
    // Fragment uint4 at word region*128 + lane2*4 =
    //   { x[rt*16+g2][ks*8+tg2], x[rt*16+g2+8][ks*8+tg2],
    //     x[rt*16+g2][ks*8+tg2+4], x[rt*16+g2+8][ks*8+tg2+4] }
    int a_r0[2], a_r1[2], a_k0[2];
    uint32_t a_dst[2];
#pragma unroll
    for (int l = 0; l < 2; l++) {
        int slot = tid + 256 * l;
        int region = slot >> 5, lane2 = slot & 31;
        int rt = region >> 2, ks2 = region & 3;
        int g2 = lane2 >> 2, tg2 = lane2 & 3;
        a_r0[l] = rt * 16 + g2;
        a_r1[l] = a_r0[l] + 8;
        a_k0[l] = ks2 * 8 + tg2;
        a_dst[l] = (uint32_t)(region * 128 + lane2 * 4);
    }

    // ---- prologue: A chunk 0 ----
#pragma unroll
    for (int l = 0; l < 2; l++) {
        const float* r0 = x + (size_t)(m0 + a_r0[l]) * F_DIM + a_k0[l];
        const float* r1 = x + (size_t)(m0 + a_r1[l]) * F_DIM + a_k0[l];
        uint4 o;
        o.x = to_tf32(__ldg(r0));
        o.y = to_tf32(__ldg(r1));
        o.z = to_tf32(__ldg(r0 + 4));
        o.w = to_tf32(__ldg(r1 + 4));
        *reinterpret_cast<uint4*>(As + a_dst[l]) = o;
    }

    // ---- main loop ----
    for (int t = 0; t < NCHUNK; t++) {
        const int p = t & 1;
        __syncthreads();   // A[p] visible; A[p^1] free

        // A(t+1) -> regs (8 LDG.32, consumed after compute)
        float pav[2][4];
        if (t + 1 < NCHUNK) {
            const int kn = (t + 1) * BK;
#pragma unroll
            for (int l = 0; l < 2; l++) {
                const float* r0 = x + (size_t)(m0 + a_r0[l]) * F_DIM + kn + a_k0[l];
                const float* r1 = x + (size_t)(m0 + a_r1[l]) * F_DIM + kn + a_k0[l];
                pav[l][0] = __ldg(r0);
                pav[l][1] = __ldg(r1);
                pav[l][2] = __ldg(r0 + 4);
                pav[l][3] = __ldg(r1 + 4);
            }
        }

        // ---- compute: A from smem, B direct from L1-resident g_Wfrag ----
        const uint32_t* Ap = As + p * A_WORDS;
        const uint2* Bg = reinterpret_cast<const uint2*>(
            g_Wfrag + t * 8192 + (wn * 4) * 512) + lane;
#pragma unroll
        for (int ks = 0; ks < 4; ks++) {
            uint32_t afr[2][4];
#pragma unroll
            for (int mt = 0; mt < 2; mt++) {
                uint4 q = *reinterpret_cast<const uint4*>(
                    Ap + ((wm * 2 + mt) * 4 + ks) * 128 + lane * 4);
                afr[mt][0] = q.x; afr[mt][1] = q.y;
                afr[mt][2] = q.z; afr[mt][3] = q.w;
            }
            uint32_t bfr[8][2];
#pragma unroll
            for (int nt = 0; nt < 8; nt++) {
                uint2 q = __ldg(Bg + (ks * 512 + nt * 64) / 2);
                bfr[nt][0] = q.x; bfr[nt][1] = q.y;
            }
#pragma unroll
            for (int mt = 0; mt < 2; mt++)
#pragma unroll
                for (int nt = 0; nt < 8; nt++)
                    MMA_TF32(acc[mt][nt], afr[mt], bfr[nt]);
        }

        // ---- commit A(t+1): cvt + STS.128, conflict-free ----
        if (t + 1 < NCHUNK) {
            uint32_t* An = As + (p ^ 1) * A_WORDS;
#pragma unroll
            for (int l = 0; l < 2; l++) {
                uint4 o;
                o.x = to_tf32(pav[l][0]);
                o.y = to_tf32(pav[l][1]);
                o.z = to_tf32(pav[l][2]);
                o.w = to_tf32(pav[l][3]);
                *reinterpret_cast<uint4*>(An + a_dst[l]) = o;
            }
        }
    }

    // ---------------- epilogue ----------------
#pragma unroll
    for (int mt = 0; mt < 2; mt++) {
#pragma unroll
        for (int half = 0; half < 2; half++) {
            int rowl = wm * 32 + mt * 16 + g + half * 8;
            float s = 0.0f;
#pragma unroll
            for (int nt = 0; nt < 8; nt++) {
#pragma unroll
                for (int j = 0; j < 2; j++) {
                    int col = wn * 64 + nt * 8 + 2 * tg + j;
                    float logit = acc[mt][nt][half * 2 + j] + s_b[col];
                    if (fabsf(logit) < TAU) {
                        int qi = atomicAdd(&s_nresc, 1);
                        if (qi < QCAP) {
                            s_q[qi] = ((uint32_t)rowl << 8) | (uint32_t)col;
                        } else {
                            const float* xr = x + (size_t)(m0 + rowl) * F_DIM;
                            const float* wr = Wm + (size_t)col * F_DIM;
                            float a = 0.0f;
                            for (int f = 0; f < F_DIM; f++)
                                a = fmaf(__ldg(xr + f), __ldg(wr + f), a);
                            if (a + s_b[col] > 0.0f) s += s_ta[col];
                        }
                    } else if (logit > 0.0f) {
                        s += s_ta[col];
                    }
                }
            }
            s += __shfl_xor_sync(0xffffffffu, s, 1);
            s += __shfl_xor_sync(0xffffffffu, s, 2);
            if (tg == 0) psum[rowl][wn] = s;
        }
    }
    __syncthreads();

    // ---- warp-cooperative rescue ----
    {
        const int nresc = min(s_nresc, QCAP);
        for (int i = wid; i < nresc; i += 8) {
            uint32_t ent = s_q[i];
            int rowl = (int)(ent >> 8);
            int col  = (int)(ent & 0xFF);
            const float* xr = x + (size_t)(m0 + rowl) * F_DIM;
            const float* wr = Wm + (size_t)col * F_DIM;
            float a0 = 0.0f, a1 = 0.0f;
#pragma unroll
            for (int j = 0; j < 16; j += 2) {
                a0 = fmaf(__ldg(xr + j * 32 + lane), __ldg(wr + j * 32 + lane), a0);
                a1 = fmaf(__ldg(xr + (j + 1) * 32 + lane), __ldg(wr + (j + 1) * 32 + lane), a1);
            }
            float a = a0 + a1;
#pragma unroll
            for (int o = 16; o > 0; o >>= 1)
                a += __shfl_xor_sync(0xffffffffu, a, o);
            if (lane == 0 && a + s_b[col] > 0.0f)
                atomicAdd(&s_rsum[rowl], s_ta[col]);
        }
    }
    __syncthreads();

    if (tid < BM) {
        float s = psum[tid][0] + psum[tid][1] + psum[tid][2] + psum[tid][3]
                + s_rsum[tid];
        out[m0 + tid] = (s > 0.0f) ? 1.0f : ((s < 0.0f) ? -1.0f : 0.0f);
    }
}

extern "C" void kernel_launch(void* const* d_in, const int* in_sizes, int n_in,
                              void* d_out, int out_size) {
    const float* x      = (const float*)d_in[0];   // [N, F]
    const float* Wm     = (const float*)d_in[1];   // [E, F]
    const float* bvec   = (const float*)d_in[2];   // [E]
    const float* alphas = (const float*)d_in[3];   // [E]
    float* out = (float*)d_out;                    // [N]

    const int E = in_sizes[2];         // 256
    const int F = in_sizes[1] / E;     // 512
    const int N = in_sizes[0] / F;     // 131072

    (void)E; (void)F;
    prep_kernel<<<(E_DIM * (F_DIM / 4)) / 256, 256>>>(Wm);

    cudaFuncSetAttribute(adaboost_mma_kernel,
                         cudaFuncAttributeMaxDynamicSharedMemorySize, DSMEM_BYTES);
    adaboost_mma_kernel<<<N / BM, 256, DSMEM_BYTES>>>(x, Wm, bvec, alphas, out);
}

// round 13
// speedup vs baseline: 2.0244x; 1.4423x over previous
#include <cuda_runtime.h>
#include <cuda_bf16.h>
#include <cstdint>

// AdaBoost fused classifier via legacy mma.sync TF32 (base-ISA sm_103).
//   logits[N,E] = x[N,F] @ W[E,F]^T + b
//   pred = (logit > 0); acc = sum_e pred*trunc(alpha); out = sign(acc)
// |logit| < TAU rescued by warp-cooperative exact fp32 recompute.
//
// R9 skeleton (BM=64, 256 thr, 2 CTAs/SM, warp tile 32x64, cp.async B
// double-buffer, fragment-order smem) with ONE change: the A-tile commit
// is now conflict-free. Each thread assembles a complete MMA fragment
// uint4 (4x LDG.32) and stores it with a single STS.128 to consecutive
// words -> A-commit wavefronts drop ~6x vs R9's scattered STS.32.

#define F_DIM 512
#define E_DIM 256
#define BM 64
#define BK 32
#define NCHUNK (F_DIM / BK)   // 16
#define TAU 4e-3f
#define QCAP 512

#define A_WORDS 2048                 // 16 regions x 128 words per buffer
#define B_WORDS 8192                 // per buffer (256n x 32k, fragment order)
#define DSMEM_BYTES ((2 * A_WORDS + 2 * B_WORDS) * 4)   // 81920

// W in tf32, fragment order: word = t*8192 + (wn*4+ks)*512 + nt*64 + lane*2 + w
__device__ uint32_t g_Wfrag[E_DIM * F_DIM];

static __device__ __forceinline__ uint32_t to_tf32(float x) {
    uint32_t r;
    asm("cvt.rna.tf32.f32 %0, %1;" : "=r"(r) : "f"(x));
    return r;
}
static __device__ __forceinline__ uint32_t smem_u32(const void* p) {
    uint32_t a;
    asm("{ .reg .u64 t; cvta.to.shared.u64 t, %1; cvt.u32.u64 %0, t; }"
        : "=r"(a) : "l"(p));
    return a;
}

#define CP_ASYNC16(dst, src) \
    asm volatile("cp.async.ca.shared.global [%0], [%1], 16;" \
                 :: "r"(dst), "l"(src) : "memory")
#define CP_COMMIT() asm volatile("cp.async.commit_group;" ::: "memory")
#define CP_WAIT_ALL() asm volatile("cp.async.wait_group 0;" ::: "memory")

#define MMA_TF32(c, a, b)                                                  \
    asm volatile(                                                          \
        "mma.sync.aligned.m16n8k8.row.col.f32.tf32.tf32.f32 "              \
        "{%0,%1,%2,%3}, {%4,%5,%6,%7}, {%8,%9}, {%0,%1,%2,%3};"            \
        : "+f"((c)[0]), "+f"((c)[1]), "+f"((c)[2]), "+f"((c)[3])           \
        : "r"((a)[0]), "r"((a)[1]), "r"((a)[2]), "r"((a)[3]),              \
          "r"((b)[0]), "r"((b)[1]))

// ---- prep: convert W to tf32 AND permute into fragment order ----
__global__ void prep_kernel(const float* __restrict__ Wm) {
    int idx = blockIdx.x * blockDim.x + threadIdx.x;   // (n, k4)
    int n  = idx >> 7;
    int k4 = idx & 127;
    float4 v = *reinterpret_cast<const float4*>(Wm + (size_t)n * F_DIM + k4 * 4);
    uint32_t c0 = to_tf32(v.x), c1 = to_tf32(v.y);
    uint32_t c2 = to_tf32(v.z), c3 = to_tf32(v.w);

    int k0 = k4 * 4;
    int t  = k0 >> 5;
    int ks = (k0 >> 3) & 3;
    int w  = (k0 & 7) >> 2;
    int wn = n >> 6, nt = (n >> 3) & 7, g = n & 7;
    uint32_t base = (uint32_t)t * 8192 + (wn * 4 + ks) * 512 + nt * 64 + g * 8 + w;
    g_Wfrag[base + 0] = c0;          // tg stride 2
    g_Wfrag[base + 2] = c1;
    g_Wfrag[base + 4] = c2;
    g_Wfrag[base + 6] = c3;
}

__global__ __launch_bounds__(256, 2)
void adaboost_mma_kernel(const float* __restrict__ x,
                         const float* __restrict__ Wm,
                         const float* __restrict__ bvec,
                         const float* __restrict__ alphas,
                         float* __restrict__ out) {
    extern __shared__ uint32_t sm[];
    uint32_t* As = sm;                       // [2][16 regions][128 words]
    uint32_t* Bs = sm + 2 * A_WORDS;         // [2][8192] fragment order

    __shared__ float s_b[E_DIM];
    __shared__ float s_ta[E_DIM];
    __shared__ float psum[BM][4];
    __shared__ float s_rsum[BM];
    __shared__ int s_nresc;
    __shared__ uint32_t s_q[QCAP];

    const int tid  = threadIdx.x;
    const int wid  = tid >> 5;
    const int lane = tid & 31;
    const int g    = lane >> 2;
    const int tg   = lane & 3;
    const int wm   = wid & 1;      // 2 warp-rows (32 rows each)
    const int wn   = wid >> 1;     // 4 warp-cols (64 cols each)
    const int m0   = blockIdx.x * BM;

    s_b[tid]  = bvec[tid];
    s_ta[tid] = truncf(alphas[tid]);
    if (tid < BM) s_rsum[tid] = 0.0f;
    if (tid == 0) s_nresc = 0;

    const uint32_t Bs_u = smem_u32(Bs);

    float acc[2][8][4];
#pragma unroll
    for (int i = 0; i < 2; i++)
#pragma unroll
        for (int j = 0; j < 8; j++)
#pragma unroll
            for (int r = 0; r < 4; r++) acc[i][j][r] = 0.0f;

    // A commit mapping: 2 slots/thread; slot -> (region = rt*4+ks, lane2).
    // Fragment uint4 at word region*128 + lane2*4 =
    //   { x[rt*16+g2][ks*8+tg2], x[rt*16+g2+8][ks*8+tg2],
    //     x[rt*16+g2][ks*8+tg2+4], x[rt*16+g2+8][ks*8+tg2+4] }
    int a_r0[2], a_r1[2], a_k0[2];
    uint32_t a_dst[2];
#pragma unroll
    for (int l = 0; l < 2; l++) {
        int slot = tid + 256 * l;
        int region = slot >> 5, lane2 = slot & 31;
        int rt = region >> 2, ks2 = region & 3;
        int g2 = lane2 >> 2, tg2 = lane2 & 3;
        a_r0[l] = rt * 16 + g2;
        a_r1[l] = a_r0[l] + 8;
        a_k0[l] = ks2 * 8 + tg2;
        a_dst[l] = (uint32_t)(region * 128 + lane2 * 4);
    }

    // ---- prologue: chunk 0 ----
#pragma unroll
    for (int l = 0; l < 8; l++) {
        int u = tid + 256 * l;
        CP_ASYNC16(Bs_u + u * 16, (const char*)(g_Wfrag + u * 4));
    }
    CP_COMMIT();
#pragma unroll
    for (int l = 0; l < 2; l++) {
        const float* r0 = x + (size_t)(m0 + a_r0[l]) * F_DIM + a_k0[l];
        const float* r1 = x + (size_t)(m0 + a_r1[l]) * F_DIM + a_k0[l];
        uint4 o;
        o.x = to_tf32(__ldg(r0));
        o.y = to_tf32(__ldg(r1));
        o.z = to_tf32(__ldg(r0 + 4));
        o.w = to_tf32(__ldg(r1 + 4));
        *reinterpret_cast<uint4*>(As + a_dst[l]) = o;
    }

    // ---- main loop ----
    for (int t = 0; t < NCHUNK; t++) {
        const int p = t & 1;
        CP_WAIT_ALL();
        __syncthreads();   // A[p], B[p] visible; [p^1] free

        // issue B(t+1)
        if (t + 1 < NCHUNK) {
#pragma unroll
            for (int l = 0; l < 8; l++) {
                int u = tid + 256 * l;
                CP_ASYNC16(Bs_u + ((p ^ 1) * B_WORDS) * 4 + u * 16,
                           (const char*)(g_Wfrag + (t + 1) * B_WORDS + u * 4));
            }
        }
        CP_COMMIT();

        // A(t+1) -> regs (8 LDG.32, consumed after compute)
        float pav[2][4];
        if (t + 1 < NCHUNK) {
            const int kn = (t + 1) * BK;
#pragma unroll
            for (int l = 0; l < 2; l++) {
                const float* r0 = x + (size_t)(m0 + a_r0[l]) * F_DIM + kn + a_k0[l];
                const float* r1 = x + (size_t)(m0 + a_r1[l]) * F_DIM + kn + a_k0[l];
                pav[l][0] = __ldg(r0);
                pav[l][1] = __ldg(r1);
                pav[l][2] = __ldg(r0 + 4);
                pav[l][3] = __ldg(r1 + 4);
            }
        }

        // ---- compute on buffer p ----
        const uint32_t* Ap = As + p * A_WORDS;
        const uint32_t* Bp = Bs + p * B_WORDS;
#pragma unroll
        for (int ks = 0; ks < 4; ks++) {
            uint32_t afr[2][4];
#pragma unroll
            for (int mt = 0; mt < 2; mt++) {
                uint4 q = *reinterpret_cast<const uint4*>(
                    Ap + ((wm * 2 + mt) * 4 + ks) * 128 + lane * 4);
                afr[mt][0] = q.x; afr[mt][1] = q.y;
                afr[mt][2] = q.z; afr[mt][3] = q.w;
            }
            uint32_t bfr[8][2];
#pragma unroll
            for (int nt = 0; nt < 8; nt++) {
                uint2 q = *reinterpret_cast<const uint2*>(
                    Bp + (wn * 4 + ks) * 512 + nt * 64 + lane * 2);
                bfr[nt][0] = q.x; bfr[nt][1] = q.y;
            }
#pragma unroll
            for (int mt = 0; mt < 2; mt++)
#pragma unroll
                for (int nt = 0; nt < 8; nt++)
                    MMA_TF32(acc[mt][nt], afr[mt], bfr[nt]);
        }

        // ---- commit A(t+1): cvt + STS.128, conflict-free ----
        if (t + 1 < NCHUNK) {
            uint32_t* An = As + (p ^ 1) * A_WORDS;
#pragma unroll
            for (int l = 0; l < 2; l++) {
                uint4 o;
                o.x = to_tf32(pav[l][0]);
                o.y = to_tf32(pav[l][1]);
                o.z = to_tf32(pav[l][2]);
                o.w = to_tf32(pav[l][3]);
                *reinterpret_cast<uint4*>(An + a_dst[l]) = o;
            }
        }
    }

    // ---------------- epilogue ----------------
#pragma unroll
    for (int mt = 0; mt < 2; mt++) {
#pragma unroll
        for (int half = 0; half < 2; half++) {
            int rowl = wm * 32 + mt * 16 + g + half * 8;
            float s = 0.0f;
#pragma unroll
            for (int nt = 0; nt < 8; nt++) {
#pragma unroll
                for (int j = 0; j < 2; j++) {
                    int col = wn * 64 + nt * 8 + 2 * tg + j;
                    float logit = acc[mt][nt][half * 2 + j] + s_b[col];
                    if (fabsf(logit) < TAU) {
                        int qi = atomicAdd(&s_nresc, 1);
                        if (qi < QCAP) {
                            s_q[qi] = ((uint32_t)rowl << 8) | (uint32_t)col;
                        } else {
                            const float* xr = x + (size_t)(m0 + rowl) * F_DIM;
                            const float* wr = Wm + (size_t)col * F_DIM;
                            float a = 0.0f;
                            for (int f = 0; f < F_DIM; f++)
                                a = fmaf(__ldg(xr + f), __ldg(wr + f), a);
                            if (a + s_b[col] > 0.0f) s += s_ta[col];
                        }
                    } else if (logit > 0.0f) {
                        s += s_ta[col];
                    }
                }
            }
            s += __shfl_xor_sync(0xffffffffu, s, 1);
            s += __shfl_xor_sync(0xffffffffu, s, 2);
            if (tg == 0) psum[rowl][wn] = s;
        }
    }
    __syncthreads();

    // ---- warp-cooperative rescue ----
    {
        const int nresc = min(s_nresc, QCAP);
        for (int i = wid; i < nresc; i += 8) {
            uint32_t ent = s_q[i];
            int rowl = (int)(ent >> 8);
            int col  = (int)(ent & 0xFF);
            const float* xr = x + (size_t)(m0 + rowl) * F_DIM;
            const float* wr = Wm + (size_t)col * F_DIM;
            float a0 = 0.0f, a1 = 0.0f;
#pragma unroll
            for (int j = 0; j < 16; j += 2) {
                a0 = fmaf(__ldg(xr + j * 32 + lane), __ldg(wr + j * 32 + lane), a0);
                a1 = fmaf(__ldg(xr + (j + 1) * 32 + lane), __ldg(wr + (j + 1) * 32 + lane), a1);
            }
            float a = a0 + a1;
#pragma unroll
            for (int o = 16; o > 0; o >>= 1)
                a += __shfl_xor_sync(0xffffffffu, a, o);
            if (lane == 0 && a + s_b[col] > 0.0f)
                atomicAdd(&s_rsum[rowl], s_ta[col]);
        }
    }
    __syncthreads();

    if (tid < BM) {
        float s = psum[tid][0] + psum[tid][1] + psum[tid][2] + psum[tid][3]
                + s_rsum[tid];
        out[m0 + tid] = (s > 0.0f) ? 1.0f : ((s < 0.0f) ? -1.0f : 0.0f);
    }
}

extern "C" void kernel_launch(void* const* d_in, const int* in_sizes, int n_in,
                              void* d_out, int out_size) {
    const float* x      = (const float*)d_in[0];   // [N, F]
    const float* Wm     = (const float*)d_in[1];   // [E, F]
    const float* bvec   = (const float*)d_in[2];   // [E]
    const float* alphas = (const float*)d_in[3];   // [E]
    float* out = (float*)d_out;                    // [N]

    const int E = in_sizes[2];         // 256
    const int F = in_sizes[1] / E;     // 512
    const int N = in_sizes[0] / F;     // 131072

    (void)E; (void)F;
    prep_kernel<<<(E_DIM * (F_DIM / 4)) / 256, 256>>>(Wm);

    cudaFuncSetAttribute(adaboost_mma_kernel,
                         cudaFuncAttributeMaxDynamicSharedMemorySize, DSMEM_BYTES);
    adaboost_mma_kernel<<<N / BM, 256, DSMEM_BYTES>>>(x, Wm, bvec, alphas, out);
}